// round 10
// baseline (speedup 1.0000x reference)
#include <cuda_runtime.h>
#include <cuda_fp16.h>
#include <cstdint>

#define NN 50000
#define NE 600000
#define DD 128
#define NL 5
#define NROWS 50048   // 782 * 64

// ---------------- scratch ----------------
__device__ int   g_is64;
__device__ int   g_deg[NN];
__device__ int   g_cursor[NN];
__device__ int   g_rowptr[NN + 1];
__device__ int   g_col[NE];
__device__ float g_h0[NN * DD];
__device__ float g_h1[NN * DD];
__device__ __half g_zh[(size_t)NROWS * DD];   // split z (hi, fp16)
__device__ __half g_zl[(size_t)NROWS * DD];   // split z (lo, fp16)

// fp16 weights, transposed: w1 as [L][256 n][128 k], w2 as [L][128 n][256 k]
__device__ __half g_w1[NL * 256 * 128];
__device__ __half g_w2[NL * 128 * 256];

#define STILE 1024
#define NTILE ((NN + STILE - 1) / STILE)
__device__ int g_tsum[NTILE];

// ---------------- helpers ----------------
__device__ __forceinline__ float leaky(float v) { return v > 0.f ? v : 0.2f * v; }

__device__ __forceinline__ void split2h(float a, float b, uint32_t& hw, uint32_t& lw) {
    __half ha = __float2half_rn(a);
    __half hb = __float2half_rn(b);
    float ra = a - __half2float(ha);
    float rb = b - __half2float(hb);
    __half la = __float2half_rn(ra);
    __half lb = __float2half_rn(rb);
    hw = (uint32_t)__half_as_ushort(ha) | ((uint32_t)__half_as_ushort(hb) << 16);
    lw = (uint32_t)__half_as_ushort(la) | ((uint32_t)__half_as_ushort(lb) << 16);
}

__device__ __forceinline__ void mma16816h(float* d, const uint32_t* a, const uint32_t* b) {
    asm volatile(
        "mma.sync.aligned.m16n8k16.row.col.f32.f16.f16.f32 "
        "{%0,%1,%2,%3}, {%4,%5,%6,%7}, {%8,%9}, {%0,%1,%2,%3};"
        : "+f"(d[0]), "+f"(d[1]), "+f"(d[2]), "+f"(d[3])
        : "r"(a[0]), "r"(a[1]), "r"(a[2]), "r"(a[3]), "r"(b[0]), "r"(b[1]));
}

__device__ __forceinline__ uint32_t smem_u32(const void* p) {
    uint32_t a;
    asm("{ .reg .u64 t; cvta.to.shared.u64 t, %1; cvt.u32.u64 %0, t; }" : "=r"(a) : "l"(p));
    return a;
}

__device__ __forceinline__ void cpa16(uint32_t dst, const void* src) {
    asm volatile("cp.async.cg.shared.global [%0], [%1], 16;" :: "r"(dst), "l"(src));
}

// ---------------- dtype detect ----------------
__global__ void detect_kernel(const int* __restrict__ p) {
    if (threadIdx.x == 0) {
        int acc = 0;
#pragma unroll
        for (int i = 0; i < 64; i++) acc |= p[2 * i + 1];
        g_is64 = (acc == 0) ? 1 : 0;
    }
}
__device__ __forceinline__ int edge_at(const int* __restrict__ p, int idx) {
    return g_is64 ? p[2 * idx] : p[idx];
}

// ---------------- CSR build ----------------
__global__ void zero_kernel() {
    int i = blockIdx.x * blockDim.x + threadIdx.x;
    if (i < NN) { g_deg[i] = 0; g_cursor[i] = 0; }
}
__global__ void hist_kernel(const int* __restrict__ ei) {
    int e = blockIdx.x * blockDim.x + threadIdx.x;
    if (e < NE) atomicAdd(&g_deg[edge_at(ei, NE + e)], 1);
}
__global__ void reduce_kernel() {
    int b = blockIdx.x, t = threadIdx.x;
    int s = 0;
#pragma unroll
    for (int j = 0; j < 4; j++) {
        int i = b * STILE + t * 4 + j;
        if (i < NN) s += g_deg[i];
    }
#pragma unroll
    for (int o = 16; o; o >>= 1) s += __shfl_down_sync(~0u, s, o);
    __shared__ int ws[8];
    if ((t & 31) == 0) ws[t >> 5] = s;
    __syncthreads();
    if (t == 0) {
        int tot = 0;
#pragma unroll
        for (int w = 0; w < 8; w++) tot += ws[w];
        g_tsum[b] = tot;
    }
}
__global__ void scantop_kernel() {
    if (threadIdx.x == 0) {
        int a = 0;
        for (int i = 0; i < NTILE; i++) { int v = g_tsum[i]; g_tsum[i] = a; a += v; }
    }
}
__global__ void scantile_kernel() {
    int b = blockIdx.x, t = threadIdx.x;
    int v[4], s = 0;
#pragma unroll
    for (int j = 0; j < 4; j++) {
        int i = b * STILE + t * 4 + j;
        int x = (i < NN) ? g_deg[i] : 0;
        s += x; v[j] = s;
    }
    __shared__ int ss[256];
    ss[t] = s;
    __syncthreads();
    for (int o = 1; o < 256; o <<= 1) {
        int x = (t >= o) ? ss[t - o] : 0;
        __syncthreads();
        ss[t] += x;
        __syncthreads();
    }
    int excl = ss[t] - s + g_tsum[b];
#pragma unroll
    for (int j = 0; j < 4; j++) {
        int i = b * STILE + t * 4 + j;
        if (i < NN) g_rowptr[i + 1] = excl + v[j];
    }
    if (b == 0 && t == 0) g_rowptr[0] = 0;
}
__global__ void fill_kernel(const int* __restrict__ ei) {
    int e = blockIdx.x * blockDim.x + threadIdx.x;
    if (e < NE) {
        int src = edge_at(ei, e);
        int dst = edge_at(ei, NE + e);
        int pos = g_rowptr[dst] + atomicAdd(&g_cursor[dst], 1);
        g_col[pos] = src;
    }
}

// ---------------- weight conversion: coalesced transpose, fp16 round ----------------
__global__ void wconv_kernel(const float* __restrict__ W1, const float* __restrict__ W2) {
    __shared__ float tile[32][33];
    int b = blockIdx.x;
    int tx = threadIdx.x & 31, ty = threadIdx.x >> 5;   // 32 x 8
    if (b < NL * 32) {
        int l = b >> 5, r = b & 31;
        int kt = r >> 3, nt = r & 7;
        const float* src = W1 + (size_t)l * 32768;
#pragma unroll
        for (int j = 0; j < 4; j++)
            tile[ty * 4 + j][tx] = __ldg(&src[(kt * 32 + ty * 4 + j) * 256 + nt * 32 + tx]);
        __syncthreads();
#pragma unroll
        for (int j = 0; j < 4; j++) {
            float w = tile[tx][ty * 4 + j];
            int n = nt * 32 + ty * 4 + j, k = kt * 32 + tx;
            g_w1[(size_t)l * 32768 + n * 128 + k] = __float2half_rn(w);
        }
    } else {
        int u = b - NL * 32;
        int l = u >> 5, r = u & 31;
        int kt = r >> 2, nt = r & 3;
        const float* src = W2 + (size_t)l * 32768;
#pragma unroll
        for (int j = 0; j < 4; j++)
            tile[ty * 4 + j][tx] = __ldg(&src[(kt * 32 + ty * 4 + j) * 128 + nt * 32 + tx]);
        __syncthreads();
#pragma unroll
        for (int j = 0; j < 4; j++) {
            float w = tile[tx][ty * 4 + j];
            int n = nt * 32 + ty * 4 + j, k = kt * 32 + tx;
            g_w2[(size_t)l * 32768 + n * 256 + k] = __float2half_rn(w);
        }
    }
}

// ---------------- aggregation: z = h + sum(neigh h), written SPLIT fp16 ----------------
__global__ __launch_bounds__(256) void aggregate_kernel(const float* __restrict__ hin) {
    int warp = (blockIdx.x * blockDim.x + threadIdx.x) >> 5;
    int lane = threadIdx.x & 31;
    if (warp >= NN) return;
    const float4* hv = (const float4*)hin;
    float4 acc = __ldg(&hv[warp * 32 + lane]);
    int beg = g_rowptr[warp];
    int end = g_rowptr[warp + 1];
    int e = beg;
    for (; e + 4 <= end; e += 4) {
        int s0 = __ldg(&g_col[e]);
        int s1 = __ldg(&g_col[e + 1]);
        int s2 = __ldg(&g_col[e + 2]);
        int s3 = __ldg(&g_col[e + 3]);
        float4 v0 = __ldg(&hv[s0 * 32 + lane]);
        float4 v1 = __ldg(&hv[s1 * 32 + lane]);
        float4 v2 = __ldg(&hv[s2 * 32 + lane]);
        float4 v3 = __ldg(&hv[s3 * 32 + lane]);
        acc.x += v0.x; acc.y += v0.y; acc.z += v0.z; acc.w += v0.w;
        acc.x += v1.x; acc.y += v1.y; acc.z += v1.z; acc.w += v1.w;
        acc.x += v2.x; acc.y += v2.y; acc.z += v2.z; acc.w += v2.w;
        acc.x += v3.x; acc.y += v3.y; acc.z += v3.z; acc.w += v3.w;
    }
    for (; e < end; e++) {
        int s = __ldg(&g_col[e]);
        float4 v = __ldg(&hv[s * 32 + lane]);
        acc.x += v.x; acc.y += v.y; acc.z += v.z; acc.w += v.w;
    }
    uint32_t h0, l0, h1, l1;
    split2h(acc.x, acc.y, h0, l0);
    split2h(acc.z, acc.w, h1, l1);
    *(uint2*)(g_zh + (size_t)warp * DD + lane * 4) = make_uint2(h0, h1);
    *(uint2*)(g_zl + (size_t)warp * DD + lane * 4) = make_uint2(l0, l1);
}

// ---------------- pipelined monolithic HMMA MLP (fp16 2-term, 2 CTAs/SM) ----------------
#define ASTR 136    // A row: 272B (4-bank rotation per row)
#define YSTR 264    // Y row: 528B (528 % 128 == 16)
#define WSTRC 72    // W chunk row: 144B (144 % 128 == 16)

#define SB1_OFF 0
#define SB2_OFF 1024
#define AH_OFF  2048
#define AL_OFF  (AH_OFF + 64 * ASTR * 2)     // 19456
#define YH_OFF  2048                         // reuses A region (A dead after c==3)
#define YL_OFF  (AL_OFF + 64 * ASTR * 2)     // 36864
#define WB_OFF  (YL_OFF + 64 * YSTR * 2)     // 70656
#define WCH     (128 * WSTRC * 2)            // 18432
#define SMEM_BYTES (WB_OFF + 2 * WCH)        // 107520  -> 2 CTAs/SM

__device__ __forceinline__ uint32_t ld16x2(const char* smem, int off_bytes) {
    return *(const uint32_t*)(smem + off_bytes);
}

// chunk order (k-outer for GEMM1):
//  i=0: W1 n[0:128)   k[0:64)     i=1: W1 n[128:256) k[0:64)
//  i=2: W1 n[0:128)   k[64:128)   i=3: W1 n[128:256) k[64:128)
//  i=4..7: W2 n[0:128) k[(i-4)*64 : +64)
__device__ __forceinline__ void stage_chunk(uint32_t sb, int i,
    const __half* w1, const __half* w2, int tid)
{
    int n = tid >> 1, half = tid & 1;
    const __half* sh;
    if (i < 4) {
        sh = w1 + (size_t)((i & 1) * 128 + n) * 128 + (i >> 1) * 64 + half * 32;
    } else {
        sh = w2 + (size_t)n * 256 + (i - 4) * 64 + half * 32;
    }
    uint32_t dh = sb + WB_OFF + (uint32_t)(i & 1) * WCH + n * (WSTRC * 2) + half * 64;
#pragma unroll
    for (int j = 0; j < 4; j++)
        cpa16(dh + j * 16, sh + j * 8);
}

// 4-ks GEMM on one W chunk: acc += A[64 x 64k @ basek] @ Wchunk(128n x 64k)^T
template<int AOH, int AOL, int ASTRB>
__device__ __forceinline__ void gemm4(char* smem, int basek, int wboff,
                                      int rg, int cg, int fr, int fk,
                                      float acc[2][4][4])
{
#pragma unroll
    for (int ks = 0; ks < 4; ks++) {
        int kA = basek + ks * 16 + fk;
        uint32_t ah[2][4], al[2][4];
#pragma unroll
        for (int s = 0; s < 2; s++) {
            int r = rg * 32 + s * 16 + fr;
            int base = r * ASTRB + kA * 2;
            ah[s][0] = ld16x2(smem + AOH, base);
            ah[s][1] = ld16x2(smem + AOH, base + 8 * ASTRB);
            ah[s][2] = ld16x2(smem + AOH, base + 16);
            ah[s][3] = ld16x2(smem + AOH, base + 8 * ASTRB + 16);
            al[s][0] = ld16x2(smem + AOL, base);
            al[s][1] = ld16x2(smem + AOL, base + 8 * ASTRB);
            al[s][2] = ld16x2(smem + AOL, base + 16);
            al[s][3] = ld16x2(smem + AOL, base + 8 * ASTRB + 16);
        }
        int k0c = ks * 16 + fk;
#pragma unroll
        for (int nt = 0; nt < 4; nt++) {
            int n = cg * 32 + nt * 8 + fr;
            int wb = wboff + n * (WSTRC * 2) + k0c * 2;
            uint32_t bh[2] = { ld16x2(smem, wb), ld16x2(smem, wb + 16) };
#pragma unroll
            for (int s = 0; s < 2; s++) {
                mma16816h(acc[s][nt], ah[s], bh);
                mma16816h(acc[s][nt], al[s], bh);
            }
        }
    }
}

__global__ __launch_bounds__(256, 2) void mlp_mma_kernel(
    const float* __restrict__ b1g, const float* __restrict__ b2g,
    const __half* __restrict__ w1, const __half* __restrict__ w2,
    float* __restrict__ out, int do_relu)
{
    extern __shared__ char smem[];
    uint32_t sb = smem_u32(smem);
    int tid = threadIdx.x, lane = tid & 31, wid = tid >> 5;
    int rg = wid & 1, cg = wid >> 1;
    int row0 = blockIdx.x * 64;
    float* sb1 = (float*)(smem + SB1_OFF);
    float* sb2 = (float*)(smem + SB2_OFF);

    sb1[tid] = __ldg(&b1g[tid]);
    if (tid < 128) sb2[tid] = __ldg(&b2g[tid]);

    // ---- stage A tile via cp.async (z already split in global) ----
    {
        int row = tid >> 2, seg = tid & 3;
        size_t o = (size_t)(row0 + row) * DD + seg * 32;
        uint32_t dh = sb + AH_OFF + row * (ASTR * 2) + seg * 64;
        uint32_t dl = sb + AL_OFF + row * (ASTR * 2) + seg * 64;
#pragma unroll
        for (int j = 0; j < 4; j++) {
            cpa16(dh + j * 16, g_zh + o + j * 8);
            cpa16(dl + j * 16, g_zl + o + j * 8);
        }
    }
    stage_chunk(sb, 0, w1, w2, tid);
    asm volatile("cp.async.commit_group;" ::: "memory");

    int fr = lane >> 2, fk = (lane & 3) * 2;
    float accA[2][4][4], accB[2][4][4];

    for (int c = 0; c < 8; c++) {
        __syncthreads();
        if (c < 7) {
            stage_chunk(sb, c + 1, w1, w2, tid);
            asm volatile("cp.async.commit_group;" ::: "memory");
            asm volatile("cp.async.wait_group 1;" ::: "memory");
        } else {
            asm volatile("cp.async.wait_group 0;" ::: "memory");
        }
        __syncthreads();

        if (c == 0) {
#pragma unroll
            for (int s = 0; s < 2; s++)
#pragma unroll
                for (int nt = 0; nt < 4; nt++)
#pragma unroll
                    for (int q = 0; q < 4; q++) { accA[s][nt][q] = 0.f; accB[s][nt][q] = 0.f; }
        }
        if (c == 4) {
#pragma unroll
            for (int s = 0; s < 2; s++)
#pragma unroll
                for (int nt = 0; nt < 4; nt++)
#pragma unroll
                    for (int q = 0; q < 4; q++) accA[s][nt][q] = 0.f;
        }

        int wboff = WB_OFF + (c & 1) * WCH;
        if (c < 4)
            gemm4<AH_OFF, AL_OFF, ASTR * 2>(smem, (c >> 1) * 64, wboff, rg, cg, fr, fk,
                                            (c & 1) ? accB : accA);
        else
            gemm4<YH_OFF, YL_OFF, YSTR * 2>(smem, (c - 4) * 64, wboff, rg, cg, fr, fk, accA);

        if (c == 3) {
            __syncthreads();   // all warps done reading A before Yh overwrites it
#pragma unroll
            for (int nh = 0; nh < 2; nh++) {
                float (*acc)[4][4] = nh ? accB : accA;
#pragma unroll
                for (int s = 0; s < 2; s++) {
                    int r = rg * 32 + s * 16 + fr;
#pragma unroll
                    for (int nt = 0; nt < 4; nt++) {
                        int cgl = nh * 128 + cg * 32 + nt * 8 + fk;
                        float bA = sb1[cgl], bB = sb1[cgl + 1];
                        uint32_t hw, lw;
                        float v0 = leaky(acc[s][nt][0] + bA);
                        float v1 = leaky(acc[s][nt][1] + bB);
                        split2h(v0, v1, hw, lw);
                        *(uint32_t*)(smem + YH_OFF + r * (YSTR * 2) + cgl * 2) = hw;
                        *(uint32_t*)(smem + YL_OFF + r * (YSTR * 2) + cgl * 2) = lw;
                        v0 = leaky(acc[s][nt][2] + bA);
                        v1 = leaky(acc[s][nt][3] + bB);
                        split2h(v0, v1, hw, lw);
                        *(uint32_t*)(smem + YH_OFF + (r + 8) * (YSTR * 2) + cgl * 2) = hw;
                        *(uint32_t*)(smem + YL_OFF + (r + 8) * (YSTR * 2) + cgl * 2) = lw;
                    }
                }
            }
        }
    }

    // ---- epilogue 2: bias [+ leaky] -> global fp32 ----
#pragma unroll
    for (int s = 0; s < 2; s++) {
        int r = rg * 32 + s * 16 + fr;
#pragma unroll
        for (int nt = 0; nt < 4; nt++) {
            int c = cg * 32 + nt * 8 + fk;
            float bA = sb2[c], bB = sb2[c + 1];
            int node = row0 + r;
            if (node < NN) {
                float v0 = accA[s][nt][0] + bA;
                float v1 = accA[s][nt][1] + bB;
                if (do_relu) { v0 = leaky(v0); v1 = leaky(v1); }
                *(float2*)(out + (size_t)node * DD + c) = make_float2(v0, v1);
            }
            if (node + 8 < NN) {
                float v0 = accA[s][nt][2] + bA;
                float v1 = accA[s][nt][3] + bB;
                if (do_relu) { v0 = leaky(v0); v1 = leaky(v1); }
                *(float2*)(out + (size_t)(node + 8) * DD + c) = make_float2(v0, v1);
            }
        }
    }
}

// ---------------- launch ----------------
extern "C" void kernel_launch(void* const* d_in, const int* in_sizes, int n_in,
                              void* d_out, int out_size) {
    const float* x  = (const float*)d_in[0];
    const int*   ei = (const int*)d_in[1];
    const float* W1 = (const float*)d_in[2];
    const float* b1 = (const float*)d_in[3];
    const float* W2 = (const float*)d_in[4];
    const float* b2 = (const float*)d_in[5];
    float* out = (float*)d_out;

    float *h0p, *h1p;
    cudaGetSymbolAddress((void**)&h0p, g_h0);
    cudaGetSymbolAddress((void**)&h1p, g_h1);
    __half *w1p, *w2p;
    cudaGetSymbolAddress((void**)&w1p, g_w1);
    cudaGetSymbolAddress((void**)&w2p, g_w2);

    cudaFuncSetAttribute(mlp_mma_kernel, cudaFuncAttributeMaxDynamicSharedMemorySize, SMEM_BYTES);

    detect_kernel<<<1, 32>>>(ei);
    zero_kernel<<<(NN + 1023) / 1024, 1024>>>();
    hist_kernel<<<(NE + 255) / 256, 256>>>(ei);
    reduce_kernel<<<NTILE, 256>>>();
    scantop_kernel<<<1, 32>>>();
    scantile_kernel<<<NTILE, 256>>>();
    fill_kernel<<<(NE + 255) / 256, 256>>>(ei);
    wconv_kernel<<<2 * NL * 32, 256>>>(W1, W2);

    const float* hin = x;
    float* bufs[2] = { h0p, h1p };
    int nblk = (NN + 63) / 64;
    for (int l = 0; l < NL; l++) {
        aggregate_kernel<<<(NN * 32 + 255) / 256, 256>>>(hin);
        float* ho = (l == NL - 1) ? out : bufs[l & 1];
        mlp_mma_kernel<<<nblk, 256, SMEM_BYTES>>>(
            b1 + (size_t)l * 2 * DD,
            b2 + (size_t)l * DD,
            w1p + (size_t)l * 256 * 128,
            w2p + (size_t)l * 128 * 256,
            ho, (l < NL - 1) ? 1 : 0);
        hin = ho;
    }
}

// round 11
// speedup vs baseline: 1.1747x; 1.1747x over previous
#include <cuda_runtime.h>
#include <cuda_fp16.h>
#include <cstdint>

#define NN 50000
#define NE 600000
#define DD 128
#define NL 5
#define NTILES 782   // ceil(50000/64)

// ---------------- scratch ----------------
__device__ int   g_is64;
__device__ int   g_deg[NN];
__device__ int   g_cursor[NN];
__device__ int   g_rowptr[NN + 1];
__device__ int   g_col[NE];
__device__ float g_h0[NN * DD];
__device__ float g_h1[NN * DD];
// split z in FRAGMENT-MAJOR tile layout: per 64-row tile, 8192 halves
// blocks (rb 0..3)*(ks 0..7), block = 256 halves (512B), in-block: lane*8 + word*2
__device__ __half g_zh[(size_t)NTILES * 8192];
__device__ __half g_zl[(size_t)NTILES * 8192];

// fp16 weights in fragment-major chunk layout:
// W1: 4 chunks (nh*2+kc) of 8192 halves; chunk blocks (nb 0..15)*(ksc 0..3), block 128 halves
// W2: 4 chunks (kc) same shape
__device__ __half g_w1[NL * 4 * 8192];
__device__ __half g_w2[NL * 4 * 8192];

#define STILE 1024
#define NTILE ((NN + STILE - 1) / STILE)
__device__ int g_tsum[NTILE];

// ---------------- helpers ----------------
__device__ __forceinline__ float leaky(float v) { return v > 0.f ? v : 0.2f * v; }

__device__ __forceinline__ void split2h(float a, float b, uint32_t& hw, uint32_t& lw) {
    __half ha = __float2half_rn(a);
    __half hb = __float2half_rn(b);
    float ra = a - __half2float(ha);
    float rb = b - __half2float(hb);
    __half la = __float2half_rn(ra);
    __half lb = __float2half_rn(rb);
    hw = (uint32_t)__half_as_ushort(ha) | ((uint32_t)__half_as_ushort(hb) << 16);
    lw = (uint32_t)__half_as_ushort(la) | ((uint32_t)__half_as_ushort(lb) << 16);
}

__device__ __forceinline__ void mma16816h(float* d, const uint32_t* a, const uint32_t* b) {
    asm volatile(
        "mma.sync.aligned.m16n8k16.row.col.f32.f16.f16.f32 "
        "{%0,%1,%2,%3}, {%4,%5,%6,%7}, {%8,%9}, {%0,%1,%2,%3};"
        : "+f"(d[0]), "+f"(d[1]), "+f"(d[2]), "+f"(d[3])
        : "r"(a[0]), "r"(a[1]), "r"(a[2]), "r"(a[3]), "r"(b[0]), "r"(b[1]));
}

__device__ __forceinline__ uint32_t smem_u32(const void* p) {
    uint32_t a;
    asm("{ .reg .u64 t; cvta.to.shared.u64 t, %1; cvt.u32.u64 %0, t; }" : "=r"(a) : "l"(p));
    return a;
}

__device__ __forceinline__ void cpa16(uint32_t dst, const void* src) {
    asm volatile("cp.async.cg.shared.global [%0], [%1], 16;" :: "r"(dst), "l"(src));
}

// ---------------- dtype detect ----------------
__global__ void detect_kernel(const int* __restrict__ p) {
    if (threadIdx.x == 0) {
        int acc = 0;
#pragma unroll
        for (int i = 0; i < 64; i++) acc |= p[2 * i + 1];
        g_is64 = (acc == 0) ? 1 : 0;
    }
}
__device__ __forceinline__ int edge_at(const int* __restrict__ p, int idx) {
    return g_is64 ? p[2 * idx] : p[idx];
}

// ---------------- CSR build ----------------
__global__ void zero_kernel() {
    int i = blockIdx.x * blockDim.x + threadIdx.x;
    if (i < NN) { g_deg[i] = 0; g_cursor[i] = 0; }
}
__global__ void hist_kernel(const int* __restrict__ ei) {
    int e = blockIdx.x * blockDim.x + threadIdx.x;
    if (e < NE) atomicAdd(&g_deg[edge_at(ei, NE + e)], 1);
}
__global__ void reduce_kernel() {
    int b = blockIdx.x, t = threadIdx.x;
    int s = 0;
#pragma unroll
    for (int j = 0; j < 4; j++) {
        int i = b * STILE + t * 4 + j;
        if (i < NN) s += g_deg[i];
    }
#pragma unroll
    for (int o = 16; o; o >>= 1) s += __shfl_down_sync(~0u, s, o);
    __shared__ int ws[8];
    if ((t & 31) == 0) ws[t >> 5] = s;
    __syncthreads();
    if (t == 0) {
        int tot = 0;
#pragma unroll
        for (int w = 0; w < 8; w++) tot += ws[w];
        g_tsum[b] = tot;
    }
}
__global__ void scantop_kernel() {
    if (threadIdx.x == 0) {
        int a = 0;
        for (int i = 0; i < NTILE; i++) { int v = g_tsum[i]; g_tsum[i] = a; a += v; }
    }
}
__global__ void scantile_kernel() {
    int b = blockIdx.x, t = threadIdx.x;
    int v[4], s = 0;
#pragma unroll
    for (int j = 0; j < 4; j++) {
        int i = b * STILE + t * 4 + j;
        int x = (i < NN) ? g_deg[i] : 0;
        s += x; v[j] = s;
    }
    __shared__ int ss[256];
    ss[t] = s;
    __syncthreads();
    for (int o = 1; o < 256; o <<= 1) {
        int x = (t >= o) ? ss[t - o] : 0;
        __syncthreads();
        ss[t] += x;
        __syncthreads();
    }
    int excl = ss[t] - s + g_tsum[b];
#pragma unroll
    for (int j = 0; j < 4; j++) {
        int i = b * STILE + t * 4 + j;
        if (i < NN) g_rowptr[i + 1] = excl + v[j];
    }
    if (b == 0 && t == 0) g_rowptr[0] = 0;
}
__global__ void fill_kernel(const int* __restrict__ ei) {
    int e = blockIdx.x * blockDim.x + threadIdx.x;
    if (e < NE) {
        int src = edge_at(ei, e);
        int dst = edge_at(ei, NE + e);
        int pos = g_rowptr[dst] + atomicAdd(&g_cursor[dst], 1);
        g_col[pos] = src;
    }
}

// ---------------- weight conversion: transpose + fragment-major blocked layout ----------------
__device__ __forceinline__ size_t wfrag_idx(int chunk, int nb, int ksc, int fr, int klocal, int kbit) {
    int word = klocal >> 3;
    int fkk = (klocal & 7) & ~1;
    int ln = fr * 4 + (fkk >> 1);
    return (size_t)chunk * 8192 + (nb * 4 + ksc) * 128 + ln * 4 + word * 2 + kbit;
}

__global__ void wconv_kernel(const float* __restrict__ W1, const float* __restrict__ W2) {
    __shared__ float tile[32][33];
    int b = blockIdx.x;
    int tx = threadIdx.x & 31, ty = threadIdx.x >> 5;   // 32 x 8
    if (b < NL * 32) {
        int l = b >> 5, r = b & 31;
        int kt = r >> 3, nt = r & 7;
        const float* src = W1 + (size_t)l * 32768;
#pragma unroll
        for (int j = 0; j < 4; j++)
            tile[ty * 4 + j][tx] = __ldg(&src[(kt * 32 + ty * 4 + j) * 256 + nt * 32 + tx]);
        __syncthreads();
#pragma unroll
        for (int j = 0; j < 4; j++) {
            float w = tile[tx][ty * 4 + j];
            int n = nt * 32 + ty * 4 + j, k = kt * 32 + tx;
            int chunk = (n >> 7) * 2 + (k >> 6);
            size_t o = (size_t)l * 32768 +
                       wfrag_idx(chunk, (n & 127) >> 3, (k & 63) >> 4, n & 7, k & 15, k & 1);
            g_w1[o] = __float2half_rn(w);
        }
    } else {
        int u = b - NL * 32;
        int l = u >> 5, r = u & 31;
        int kt = r >> 2, nt = r & 3;
        const float* src = W2 + (size_t)l * 32768;
#pragma unroll
        for (int j = 0; j < 4; j++)
            tile[ty * 4 + j][tx] = __ldg(&src[(kt * 32 + ty * 4 + j) * 128 + nt * 32 + tx]);
        __syncthreads();
#pragma unroll
        for (int j = 0; j < 4; j++) {
            float w = tile[tx][ty * 4 + j];
            int n = nt * 32 + ty * 4 + j, k = kt * 32 + tx;
            int chunk = k >> 6;
            size_t o = (size_t)l * 32768 +
                       wfrag_idx(chunk, n >> 3, (k & 63) >> 4, n & 7, k & 15, k & 1);
            g_w2[o] = __float2half_rn(w);
        }
    }
}

// ---------------- aggregation: z = h + sum(neigh h), SPLIT fp16, fragment-major ----------------
__global__ __launch_bounds__(256) void aggregate_kernel(const float* __restrict__ hin) {
    int node = (blockIdx.x * blockDim.x + threadIdx.x) >> 5;
    int lane = threadIdx.x & 31;
    if (node >= NN) return;
    const float4* hv = (const float4*)hin;
    float4 acc = __ldg(&hv[node * 32 + lane]);
    int beg = g_rowptr[node];
    int end = g_rowptr[node + 1];
    int e = beg;
    for (; e + 4 <= end; e += 4) {
        int s0 = __ldg(&g_col[e]);
        int s1 = __ldg(&g_col[e + 1]);
        int s2 = __ldg(&g_col[e + 2]);
        int s3 = __ldg(&g_col[e + 3]);
        float4 v0 = __ldg(&hv[s0 * 32 + lane]);
        float4 v1 = __ldg(&hv[s1 * 32 + lane]);
        float4 v2 = __ldg(&hv[s2 * 32 + lane]);
        float4 v3 = __ldg(&hv[s3 * 32 + lane]);
        acc.x += v0.x; acc.y += v0.y; acc.z += v0.z; acc.w += v0.w;
        acc.x += v1.x; acc.y += v1.y; acc.z += v1.z; acc.w += v1.w;
        acc.x += v2.x; acc.y += v2.y; acc.z += v2.z; acc.w += v2.w;
        acc.x += v3.x; acc.y += v3.y; acc.z += v3.z; acc.w += v3.w;
    }
    for (; e < end; e++) {
        int s = __ldg(&g_col[e]);
        float4 v = __ldg(&hv[s * 32 + lane]);
        acc.x += v.x; acc.y += v.y; acc.z += v.z; acc.w += v.w;
    }
    // fragment-major store: lane owns cols [4*lane, 4*lane+4)
    int tile = node >> 6, rr = node & 63;
    int rb = rr >> 4, fr8 = rr & 15;
    int wrow = fr8 >> 3;            // +1 if row in upper half of 16
    int fr = fr8 & 7;
    int l3 = lane & 3;
    int klocal = 4 * l3;            // 0,4,8,12
    int whigh = (klocal >= 8) ? 2 : 0;
    int lane1 = fr * 4 + ((l3 & 1) ? 2 : 0);
    int w = wrow + whigh;
    size_t base = (size_t)tile * 8192 + (size_t)(rb * 8 + (lane >> 2)) * 256;
    size_t idx1 = base + lane1 * 8 + w * 2;
    size_t idx2 = idx1 + 8;        // lane1+1 slot
    uint32_t h0, l0, h1, l1;
    split2h(acc.x, acc.y, h0, l0);
    split2h(acc.z, acc.w, h1, l1);
    *(uint32_t*)(g_zh + idx1) = h0;
    *(uint32_t*)(g_zh + idx2) = h1;
    *(uint32_t*)(g_zl + idx1) = l0;
    *(uint32_t*)(g_zl + idx2) = l1;
}

// ---------------- pipelined HMMA MLP (fp16 2-term, fragment-major, vector LDS) ----------------
#define SB1_OFF 0
#define SB2_OFF 1024
#define AH_OFF  2048
#define AL_OFF  (AH_OFF + 16384)    // 18432
#define YH_OFF  (AL_OFF + 16384)    // 34816
#define YL_OFF  (YH_OFF + 32768)    // 67584
#define WB_OFF  (YL_OFF + 32768)    // 100352
#define WCH     16384
#define SMEM_BYTES (WB_OFF + 2 * WCH)  // 133120

// stage chunk i (0..3: W1 chunk i; 4..7: W2 chunk i-4) into buffer i&1; 1024 x 16B linear
__device__ __forceinline__ void stage_chunk(uint32_t sb, int i,
    const __half* w1, const __half* w2, int tid)
{
    const __half* src = (i < 4) ? (w1 + (size_t)i * 8192) : (w2 + (size_t)(i - 4) * 8192);
    uint32_t dst = sb + WB_OFF + (uint32_t)(i & 1) * WCH;
#pragma unroll
    for (int j = 0; j < 4; j++) {
        int idx = tid + j * 256;
        cpa16(dst + idx * 16, src + idx * 8);
    }
}

// 4-ks GEMM on one W chunk (fragment-major): A via LDS.128, W via LDS.64
template<int RBS>
__device__ __forceinline__ void gemm4f(const char* smem, int aoh, int aol, int ksbase, int wboff,
                                       int rg, int cg, int lane, float acc[2][4][4])
{
#pragma unroll
    for (int ks = 0; ks < 4; ks++) {
        uint4 ah[2], al[2];
#pragma unroll
        for (int s = 0; s < 2; s++) {
            int off = ((rg * 2 + s) * RBS + ksbase + ks) * 512 + lane * 16;
            ah[s] = *(const uint4*)(smem + aoh + off);
            al[s] = *(const uint4*)(smem + aol + off);
        }
#pragma unroll
        for (int nt = 0; nt < 4; nt++) {
            uint2 b = *(const uint2*)(smem + wboff + ((cg * 4 + nt) * 4 + ks) * 256 + lane * 8);
            uint32_t bh[2] = { b.x, b.y };
#pragma unroll
            for (int s = 0; s < 2; s++) {
                mma16816h(acc[s][nt], (const uint32_t*)&ah[s], bh);
                mma16816h(acc[s][nt], (const uint32_t*)&al[s], bh);
            }
        }
    }
}

__global__ __launch_bounds__(256, 1) void mlp_mma_kernel(
    const float* __restrict__ b1g, const float* __restrict__ b2g,
    const __half* __restrict__ w1, const __half* __restrict__ w2,
    float* __restrict__ out, int do_relu)
{
    extern __shared__ char smem[];
    uint32_t sb = smem_u32(smem);
    int tid = threadIdx.x, lane = tid & 31, wid = tid >> 5;
    int rg = wid & 1, cg = wid >> 1;
    int row0 = blockIdx.x * 64;
    float* sb1 = (float*)(smem + SB1_OFF);
    float* sb2 = (float*)(smem + SB2_OFF);

    sb1[tid] = __ldg(&b1g[tid]);
    if (tid < 128) sb2[tid] = __ldg(&b2g[tid]);

    // ---- stage A tile (fragment-major in global already): pure linear copy ----
    {
        size_t o = (size_t)blockIdx.x * 8192;
#pragma unroll
        for (int j = 0; j < 4; j++) {
            int idx = tid + j * 256;
            cpa16(sb + AH_OFF + idx * 16, g_zh + o + idx * 8);
            cpa16(sb + AL_OFF + idx * 16, g_zl + o + idx * 8);
        }
    }
    stage_chunk(sb, 0, w1, w2, tid);
    asm volatile("cp.async.commit_group;" ::: "memory");

    int fr = lane >> 2, fk = (lane & 3) * 2;
    float acc[2][4][4];

    for (int c = 0; c < 8; c++) {
        __syncthreads();
        if (c < 7) {
            stage_chunk(sb, c + 1, w1, w2, tid);
            asm volatile("cp.async.commit_group;" ::: "memory");
            asm volatile("cp.async.wait_group 1;" ::: "memory");
        } else {
            asm volatile("cp.async.wait_group 0;" ::: "memory");
        }
        __syncthreads();

        if (c == 0 || c == 2 || c == 4) {
#pragma unroll
            for (int s = 0; s < 2; s++)
#pragma unroll
                for (int nt = 0; nt < 4; nt++)
#pragma unroll
                    for (int q = 0; q < 4; q++) acc[s][nt][q] = 0.f;
        }

        int wboff = WB_OFF + (c & 1) * WCH;
        if (c < 4)
            gemm4f<8>(smem, AH_OFF, AL_OFF, (c & 1) * 4, wboff, rg, cg, lane, acc);
        else
            gemm4f<16>(smem, YH_OFF, YL_OFF, (c - 4) * 4, wboff, rg, cg, lane, acc);

        if (c == 1 || c == 3) {
            // epilogue 1: bias + leaky, split fp16 -> Y (fragment-major, vector STS)
            int nh = c >> 1;
#pragma unroll
            for (int s = 0; s < 2; s++) {
#pragma unroll
                for (int p = 0; p < 2; p++) {
                    float* aE = acc[s][2 * p];
                    float* aO = acc[s][2 * p + 1];
                    int cglE = nh * 128 + cg * 32 + (2 * p) * 8 + fk;
                    float bE0 = sb1[cglE], bE1 = sb1[cglE + 1];
                    float bO0 = sb1[cglE + 8], bO1 = sb1[cglE + 9];
                    uint4 hv, lv;
                    split2h(leaky(aE[0] + bE0), leaky(aE[1] + bE1), hv.x, lv.x);
                    split2h(leaky(aE[2] + bE0), leaky(aE[3] + bE1), hv.y, lv.y);
                    split2h(leaky(aO[0] + bO0), leaky(aO[1] + bO1), hv.z, lv.z);
                    split2h(leaky(aO[2] + bO0), leaky(aO[3] + bO1), hv.w, lv.w);
                    int off = ((rg * 2 + s) * 16 + nh * 8 + cg * 2 + p) * 512 + lane * 16;
                    *(uint4*)(smem + YH_OFF + off) = hv;
                    *(uint4*)(smem + YL_OFF + off) = lv;
                }
            }
        }
    }

    // ---- epilogue 2: bias [+ leaky] -> global fp32 (row-major) ----
#pragma unroll
    for (int s = 0; s < 2; s++) {
        int r = rg * 32 + s * 16 + fr;
#pragma unroll
        for (int nt = 0; nt < 4; nt++) {
            int c = cg * 32 + nt * 8 + fk;
            float bA = sb2[c], bB = sb2[c + 1];
            int node = row0 + r;
            if (node < NN) {
                float v0 = acc[s][nt][0] + bA;
                float v1 = acc[s][nt][1] + bB;
                if (do_relu) { v0 = leaky(v0); v1 = leaky(v1); }
                *(float2*)(out + (size_t)node * DD + c) = make_float2(v0, v1);
            }
            if (node + 8 < NN) {
                float v0 = acc[s][nt][2] + bA;
                float v1 = acc[s][nt][3] + bB;
                if (do_relu) { v0 = leaky(v0); v1 = leaky(v1); }
                *(float2*)(out + (size_t)(node + 8) * DD + c) = make_float2(v0, v1);
            }
        }
    }
}

// ---------------- launch ----------------
extern "C" void kernel_launch(void* const* d_in, const int* in_sizes, int n_in,
                              void* d_out, int out_size) {
    const float* x  = (const float*)d_in[0];
    const int*   ei = (const int*)d_in[1];
    const float* W1 = (const float*)d_in[2];
    const float* b1 = (const float*)d_in[3];
    const float* W2 = (const float*)d_in[4];
    const float* b2 = (const float*)d_in[5];
    float* out = (float*)d_out;

    float *h0p, *h1p;
    cudaGetSymbolAddress((void**)&h0p, g_h0);
    cudaGetSymbolAddress((void**)&h1p, g_h1);
    __half *w1p, *w2p;
    cudaGetSymbolAddress((void**)&w1p, g_w1);
    cudaGetSymbolAddress((void**)&w2p, g_w2);

    cudaFuncSetAttribute(mlp_mma_kernel, cudaFuncAttributeMaxDynamicSharedMemorySize, SMEM_BYTES);

    detect_kernel<<<1, 32>>>(ei);
    zero_kernel<<<(NN + 1023) / 1024, 1024>>>();
    hist_kernel<<<(NE + 255) / 256, 256>>>(ei);
    reduce_kernel<<<NTILE, 256>>>();
    scantop_kernel<<<1, 32>>>();
    scantile_kernel<<<NTILE, 256>>>();
    fill_kernel<<<(NE + 255) / 256, 256>>>(ei);
    wconv_kernel<<<2 * NL * 32, 256>>>(W1, W2);

    const float* hin = x;
    float* bufs[2] = { h0p, h1p };
    for (int l = 0; l < NL; l++) {
        aggregate_kernel<<<(NN * 32 + 255) / 256, 256>>>(hin);
        float* ho = (l == NL - 1) ? out : bufs[l & 1];
        mlp_mma_kernel<<<NTILES, 256, SMEM_BYTES>>>(
            b1 + (size_t)l * 2 * DD,
            b2 + (size_t)l * DD,
            w1p + (size_t)l * 32768,
            w2p + (size_t)l * 32768,
            ho, (l < NL - 1) ? 1 : 0);
        hin = ho;
    }
}

// round 12
// speedup vs baseline: 1.2695x; 1.0806x over previous
#include <cuda_runtime.h>
#include <cuda_fp16.h>
#include <cstdint>

#define NN 50000
#define NE 600000
#define DD 128
#define NL 5
#define NTILES 391   // ceil(50000/128)

// ---------------- scratch ----------------
__device__ int   g_is64;
__device__ int   g_deg[NN];
__device__ int   g_cursor[NN];
__device__ int   g_rowptr[NN + 1];
__device__ int   g_col[NE];
__device__ float g_h0[NN * DD];
__device__ float g_h1[NN * DD];
// split z in FRAGMENT-MAJOR tile layout: per 128-row tile, 16384 halves
// blocks (rb 0..7)*(ks 0..7), block = 256 halves (512B), in-block: lane*8 + word*2
__device__ __half g_zh[(size_t)NTILES * 16384];
__device__ __half g_zl[(size_t)NTILES * 16384];

// fp16 weights in fragment-major chunk layout (identical to R11):
__device__ __half g_w1[NL * 4 * 8192];
__device__ __half g_w2[NL * 4 * 8192];

#define STILE 1024
#define NTILE ((NN + STILE - 1) / STILE)
__device__ int g_tsum[NTILE];

// ---------------- helpers ----------------
__device__ __forceinline__ float leaky(float v) { return v > 0.f ? v : 0.2f * v; }

__device__ __forceinline__ void split2h(float a, float b, uint32_t& hw, uint32_t& lw) {
    __half ha = __float2half_rn(a);
    __half hb = __float2half_rn(b);
    float ra = a - __half2float(ha);
    float rb = b - __half2float(hb);
    __half la = __float2half_rn(ra);
    __half lb = __float2half_rn(rb);
    hw = (uint32_t)__half_as_ushort(ha) | ((uint32_t)__half_as_ushort(hb) << 16);
    lw = (uint32_t)__half_as_ushort(la) | ((uint32_t)__half_as_ushort(lb) << 16);
}

__device__ __forceinline__ void mma16816h(float* d, const uint32_t* a, const uint32_t* b) {
    asm volatile(
        "mma.sync.aligned.m16n8k16.row.col.f32.f16.f16.f32 "
        "{%0,%1,%2,%3}, {%4,%5,%6,%7}, {%8,%9}, {%0,%1,%2,%3};"
        : "+f"(d[0]), "+f"(d[1]), "+f"(d[2]), "+f"(d[3])
        : "r"(a[0]), "r"(a[1]), "r"(a[2]), "r"(a[3]), "r"(b[0]), "r"(b[1]));
}

__device__ __forceinline__ uint32_t smem_u32(const void* p) {
    uint32_t a;
    asm("{ .reg .u64 t; cvta.to.shared.u64 t, %1; cvt.u32.u64 %0, t; }" : "=r"(a) : "l"(p));
    return a;
}

__device__ __forceinline__ void cpa16(uint32_t dst, const void* src) {
    asm volatile("cp.async.cg.shared.global [%0], [%1], 16;" :: "r"(dst), "l"(src));
}

// ---------------- dtype detect ----------------
__global__ void detect_kernel(const int* __restrict__ p) {
    if (threadIdx.x == 0) {
        int acc = 0;
#pragma unroll
        for (int i = 0; i < 64; i++) acc |= p[2 * i + 1];
        g_is64 = (acc == 0) ? 1 : 0;
    }
}
__device__ __forceinline__ int edge_at(const int* __restrict__ p, int idx) {
    return g_is64 ? p[2 * idx] : p[idx];
}

// ---------------- CSR build ----------------
__global__ void zero_kernel() {
    int i = blockIdx.x * blockDim.x + threadIdx.x;
    if (i < NN) { g_deg[i] = 0; g_cursor[i] = 0; }
}
__global__ void hist_kernel(const int* __restrict__ ei) {
    int e = blockIdx.x * blockDim.x + threadIdx.x;
    if (e < NE) atomicAdd(&g_deg[edge_at(ei, NE + e)], 1);
}
__global__ void reduce_kernel() {
    int b = blockIdx.x, t = threadIdx.x;
    int s = 0;
#pragma unroll
    for (int j = 0; j < 4; j++) {
        int i = b * STILE + t * 4 + j;
        if (i < NN) s += g_deg[i];
    }
#pragma unroll
    for (int o = 16; o; o >>= 1) s += __shfl_down_sync(~0u, s, o);
    __shared__ int ws[8];
    if ((t & 31) == 0) ws[t >> 5] = s;
    __syncthreads();
    if (t == 0) {
        int tot = 0;
#pragma unroll
        for (int w = 0; w < 8; w++) tot += ws[w];
        g_tsum[b] = tot;
    }
}
__global__ void scantop_kernel() {
    if (threadIdx.x == 0) {
        int a = 0;
        for (int i = 0; i < NTILE; i++) { int v = g_tsum[i]; g_tsum[i] = a; a += v; }
    }
}
__global__ void scantile_kernel() {
    int b = blockIdx.x, t = threadIdx.x;
    int v[4], s = 0;
#pragma unroll
    for (int j = 0; j < 4; j++) {
        int i = b * STILE + t * 4 + j;
        int x = (i < NN) ? g_deg[i] : 0;
        s += x; v[j] = s;
    }
    __shared__ int ss[256];
    ss[t] = s;
    __syncthreads();
    for (int o = 1; o < 256; o <<= 1) {
        int x = (t >= o) ? ss[t - o] : 0;
        __syncthreads();
        ss[t] += x;
        __syncthreads();
    }
    int excl = ss[t] - s + g_tsum[b];
#pragma unroll
    for (int j = 0; j < 4; j++) {
        int i = b * STILE + t * 4 + j;
        if (i < NN) g_rowptr[i + 1] = excl + v[j];
    }
    if (b == 0 && t == 0) g_rowptr[0] = 0;
}
__global__ void fill_kernel(const int* __restrict__ ei) {
    int e = blockIdx.x * blockDim.x + threadIdx.x;
    if (e < NE) {
        int src = edge_at(ei, e);
        int dst = edge_at(ei, NE + e);
        int pos = g_rowptr[dst] + atomicAdd(&g_cursor[dst], 1);
        g_col[pos] = src;
    }
}

// ---------------- weight conversion: transpose + fragment-major blocked layout ----------------
__device__ __forceinline__ size_t wfrag_idx(int chunk, int nb, int ksc, int fr, int klocal, int kbit) {
    int word = klocal >> 3;
    int fkk = (klocal & 7) & ~1;
    int ln = fr * 4 + (fkk >> 1);
    return (size_t)chunk * 8192 + (nb * 4 + ksc) * 128 + ln * 4 + word * 2 + kbit;
}

__global__ void wconv_kernel(const float* __restrict__ W1, const float* __restrict__ W2) {
    __shared__ float tile[32][33];
    int b = blockIdx.x;
    int tx = threadIdx.x & 31, ty = threadIdx.x >> 5;   // 32 x 8
    if (b < NL * 32) {
        int l = b >> 5, r = b & 31;
        int kt = r >> 3, nt = r & 7;
        const float* src = W1 + (size_t)l * 32768;
#pragma unroll
        for (int j = 0; j < 4; j++)
            tile[ty * 4 + j][tx] = __ldg(&src[(kt * 32 + ty * 4 + j) * 256 + nt * 32 + tx]);
        __syncthreads();
#pragma unroll
        for (int j = 0; j < 4; j++) {
            float w = tile[tx][ty * 4 + j];
            int n = nt * 32 + ty * 4 + j, k = kt * 32 + tx;
            int chunk = (n >> 7) * 2 + (k >> 6);
            size_t o = (size_t)l * 32768 +
                       wfrag_idx(chunk, (n & 127) >> 3, (k & 63) >> 4, n & 7, k & 15, k & 1);
            g_w1[o] = __float2half_rn(w);
        }
    } else {
        int u = b - NL * 32;
        int l = u >> 5, r = u & 31;
        int kt = r >> 2, nt = r & 3;
        const float* src = W2 + (size_t)l * 32768;
#pragma unroll
        for (int j = 0; j < 4; j++)
            tile[ty * 4 + j][tx] = __ldg(&src[(kt * 32 + ty * 4 + j) * 128 + nt * 32 + tx]);
        __syncthreads();
#pragma unroll
        for (int j = 0; j < 4; j++) {
            float w = tile[tx][ty * 4 + j];
            int n = nt * 32 + ty * 4 + j, k = kt * 32 + tx;
            int chunk = k >> 6;
            size_t o = (size_t)l * 32768 +
                       wfrag_idx(chunk, n >> 3, (k & 63) >> 4, n & 7, k & 15, k & 1);
            g_w2[o] = __float2half_rn(w);
        }
    }
}

// ---------------- aggregation: z = h + sum(neigh h), SPLIT fp16, fragment-major ----------------
__global__ __launch_bounds__(256) void aggregate_kernel(const float* __restrict__ hin) {
    int node = (blockIdx.x * blockDim.x + threadIdx.x) >> 5;
    int lane = threadIdx.x & 31;
    if (node >= NN) return;
    const float4* hv = (const float4*)hin;
    float4 acc = __ldg(&hv[node * 32 + lane]);
    int beg = g_rowptr[node];
    int end = g_rowptr[node + 1];
    int e = beg;
    for (; e + 4 <= end; e += 4) {
        int s0 = __ldg(&g_col[e]);
        int s1 = __ldg(&g_col[e + 1]);
        int s2 = __ldg(&g_col[e + 2]);
        int s3 = __ldg(&g_col[e + 3]);
        float4 v0 = __ldg(&hv[s0 * 32 + lane]);
        float4 v1 = __ldg(&hv[s1 * 32 + lane]);
        float4 v2 = __ldg(&hv[s2 * 32 + lane]);
        float4 v3 = __ldg(&hv[s3 * 32 + lane]);
        acc.x += v0.x; acc.y += v0.y; acc.z += v0.z; acc.w += v0.w;
        acc.x += v1.x; acc.y += v1.y; acc.z += v1.z; acc.w += v1.w;
        acc.x += v2.x; acc.y += v2.y; acc.z += v2.z; acc.w += v2.w;
        acc.x += v3.x; acc.y += v3.y; acc.z += v3.z; acc.w += v3.w;
    }
    for (; e < end; e++) {
        int s = __ldg(&g_col[e]);
        float4 v = __ldg(&hv[s * 32 + lane]);
        acc.x += v.x; acc.y += v.y; acc.z += v.z; acc.w += v.w;
    }
    // fragment-major store (128-row tiles): lane owns cols [4*lane, 4*lane+4)
    int tile = node >> 7, rr = node & 127;
    int rb = rr >> 4, fr8 = rr & 15;
    int wrow = fr8 >> 3;
    int fr = fr8 & 7;
    int l3 = lane & 3;
    int klocal = 4 * l3;
    int whigh = (klocal >= 8) ? 2 : 0;
    int lane1 = fr * 4 + ((l3 & 1) ? 2 : 0);
    int w = wrow + whigh;
    size_t base = (size_t)tile * 16384 + (size_t)(rb * 8 + (lane >> 2)) * 256;
    size_t idx1 = base + lane1 * 8 + w * 2;
    size_t idx2 = idx1 + 8;
    uint32_t h0, l0, h1, l1;
    split2h(acc.x, acc.y, h0, l0);
    split2h(acc.z, acc.w, h1, l1);
    *(uint32_t*)(g_zh + idx1) = h0;
    *(uint32_t*)(g_zh + idx2) = h1;
    *(uint32_t*)(g_zl + idx1) = l0;
    *(uint32_t*)(g_zl + idx2) = l1;
}

// ---------------- pipelined HMMA MLP: 128-row tile, 512 threads ----------------
#define SB1_OFF 0
#define SB2_OFF 1024
#define AH_OFF  2048
#define AL_OFF  (AH_OFF + 32768)    // 34816
#define YH_OFF  (AL_OFF + 32768)    // 67584
#define YL_OFF  (YH_OFF + 65536)    // 133120
#define WB_OFF  (YL_OFF + 65536)    // 198656
#define WCH     16384
#define SMEM_BYTES (WB_OFF + 2 * WCH)  // 231424

// stage chunk i (0..3: W1 chunk i; 4..7: W2 chunk i-4) into buffer i&1; 1024 x 16B linear
__device__ __forceinline__ void stage_chunk(uint32_t sb, int i,
    const __half* w1, const __half* w2, int tid)
{
    const __half* src = (i < 4) ? (w1 + (size_t)i * 8192) : (w2 + (size_t)(i - 4) * 8192);
    uint32_t dst = sb + WB_OFF + (uint32_t)(i & 1) * WCH;
#pragma unroll
    for (int j = 0; j < 2; j++) {
        int idx = tid + j * 512;
        cpa16(dst + idx * 16, src + idx * 8);
    }
}

// 4-ks GEMM on one W chunk (fragment-major): A via LDS.128, W via LDS.64
template<int RBS>
__device__ __forceinline__ void gemm4f(const char* smem, int aoh, int aol, int ksbase, int wboff,
                                       int rg, int cg, int lane, float acc[2][4][4])
{
#pragma unroll
    for (int ks = 0; ks < 4; ks++) {
        uint4 ah[2], al[2];
#pragma unroll
        for (int s = 0; s < 2; s++) {
            int off = ((rg * 2 + s) * RBS + ksbase + ks) * 512 + lane * 16;
            ah[s] = *(const uint4*)(smem + aoh + off);
            al[s] = *(const uint4*)(smem + aol + off);
        }
#pragma unroll
        for (int nt = 0; nt < 4; nt++) {
            uint2 b = *(const uint2*)(smem + wboff + ((cg * 4 + nt) * 4 + ks) * 256 + lane * 8);
            uint32_t bh[2] = { b.x, b.y };
#pragma unroll
            for (int s = 0; s < 2; s++) {
                mma16816h(acc[s][nt], (const uint32_t*)&ah[s], bh);
                mma16816h(acc[s][nt], (const uint32_t*)&al[s], bh);
            }
        }
    }
}

__global__ __launch_bounds__(512, 1) void mlp_mma_kernel(
    const float* __restrict__ b1g, const float* __restrict__ b2g,
    const __half* __restrict__ w1, const __half* __restrict__ w2,
    float* __restrict__ out, int do_relu)
{
    extern __shared__ char smem[];
    uint32_t sb = smem_u32(smem);
    int tid = threadIdx.x, lane = tid & 31, wid = tid >> 5;
    int rg = wid & 3, cg = wid >> 2;      // 4 row-groups x 4 col-groups
    int row0 = blockIdx.x * 128;
    float* sb1 = (float*)(smem + SB1_OFF);
    float* sb2 = (float*)(smem + SB2_OFF);

    if (tid < 256) sb1[tid] = __ldg(&b1g[tid]);
    else if (tid < 384) sb2[tid - 256] = __ldg(&b2g[tid - 256]);

    // ---- stage A tile (fragment-major in global): pure linear copy ----
    {
        size_t o = (size_t)blockIdx.x * 16384;
#pragma unroll
        for (int j = 0; j < 4; j++) {
            int idx = tid + j * 512;
            cpa16(sb + AH_OFF + idx * 16, g_zh + o + idx * 8);
            cpa16(sb + AL_OFF + idx * 16, g_zl + o + idx * 8);
        }
    }
    stage_chunk(sb, 0, w1, w2, tid);
    asm volatile("cp.async.commit_group;" ::: "memory");

    int fr = lane >> 2, fk = (lane & 3) * 2;
    float acc[2][4][4];

    for (int c = 0; c < 8; c++) {
        __syncthreads();
        if (c < 7) {
            stage_chunk(sb, c + 1, w1, w2, tid);
            asm volatile("cp.async.commit_group;" ::: "memory");
            asm volatile("cp.async.wait_group 1;" ::: "memory");
        } else {
            asm volatile("cp.async.wait_group 0;" ::: "memory");
        }
        __syncthreads();

        if (c == 0 || c == 2 || c == 4) {
#pragma unroll
            for (int s = 0; s < 2; s++)
#pragma unroll
                for (int nt = 0; nt < 4; nt++)
#pragma unroll
                    for (int q = 0; q < 4; q++) acc[s][nt][q] = 0.f;
        }

        int wboff = WB_OFF + (c & 1) * WCH;
        if (c < 4)
            gemm4f<8>(smem, AH_OFF, AL_OFF, (c & 1) * 4, wboff, rg, cg, lane, acc);
        else
            gemm4f<16>(smem, YH_OFF, YL_OFF, (c - 4) * 4, wboff, rg, cg, lane, acc);

        if (c == 1 || c == 3) {
            // epilogue 1: bias + leaky, split fp16 -> Y (fragment-major, vector STS)
            int nh = c >> 1;
#pragma unroll
            for (int s = 0; s < 2; s++) {
#pragma unroll
                for (int p = 0; p < 2; p++) {
                    float* aE = acc[s][2 * p];
                    float* aO = acc[s][2 * p + 1];
                    int cglE = nh * 128 + cg * 32 + (2 * p) * 8 + fk;
                    float bE0 = sb1[cglE], bE1 = sb1[cglE + 1];
                    float bO0 = sb1[cglE + 8], bO1 = sb1[cglE + 9];
                    uint4 hv, lv;
                    split2h(leaky(aE[0] + bE0), leaky(aE[1] + bE1), hv.x, lv.x);
                    split2h(leaky(aE[2] + bE0), leaky(aE[3] + bE1), hv.y, lv.y);
                    split2h(leaky(aO[0] + bO0), leaky(aO[1] + bO1), hv.z, lv.z);
                    split2h(leaky(aO[2] + bO0), leaky(aO[3] + bO1), hv.w, lv.w);
                    int off = ((rg * 2 + s) * 16 + nh * 8 + cg * 2 + p) * 512 + lane * 16;
                    *(uint4*)(smem + YH_OFF + off) = hv;
                    *(uint4*)(smem + YL_OFF + off) = lv;
                }
            }
        }
    }

    // ---- epilogue 2: bias [+ leaky] -> global fp32 (row-major) ----
#pragma unroll
    for (int s = 0; s < 2; s++) {
        int r = rg * 32 + s * 16 + fr;
#pragma unroll
        for (int nt = 0; nt < 4; nt++) {
            int c = cg * 32 + nt * 8 + fk;
            float bA = sb2[c], bB = sb2[c + 1];
            int node = row0 + r;
            if (node < NN) {
                float v0 = acc[s][nt][0] + bA;
                float v1 = acc[s][nt][1] + bB;
                if (do_relu) { v0 = leaky(v0); v1 = leaky(v1); }
                *(float2*)(out + (size_t)node * DD + c) = make_float2(v0, v1);
            }
            if (node + 8 < NN) {
                float v0 = acc[s][nt][2] + bA;
                float v1 = acc[s][nt][3] + bB;
                if (do_relu) { v0 = leaky(v0); v1 = leaky(v1); }
                *(float2*)(out + (size_t)(node + 8) * DD + c) = make_float2(v0, v1);
            }
        }
    }
}

// ---------------- launch ----------------
extern "C" void kernel_launch(void* const* d_in, const int* in_sizes, int n_in,
                              void* d_out, int out_size) {
    const float* x  = (const float*)d_in[0];
    const int*   ei = (const int*)d_in[1];
    const float* W1 = (const float*)d_in[2];
    const float* b1 = (const float*)d_in[3];
    const float* W2 = (const float*)d_in[4];
    const float* b2 = (const float*)d_in[5];
    float* out = (float*)d_out;

    float *h0p, *h1p;
    cudaGetSymbolAddress((void**)&h0p, g_h0);
    cudaGetSymbolAddress((void**)&h1p, g_h1);
    __half *w1p, *w2p;
    cudaGetSymbolAddress((void**)&w1p, g_w1);
    cudaGetSymbolAddress((void**)&w2p, g_w2);

    cudaFuncSetAttribute(mlp_mma_kernel, cudaFuncAttributeMaxDynamicSharedMemorySize, SMEM_BYTES);

    detect_kernel<<<1, 32>>>(ei);
    zero_kernel<<<(NN + 1023) / 1024, 1024>>>();
    hist_kernel<<<(NE + 255) / 256, 256>>>(ei);
    reduce_kernel<<<NTILE, 256>>>();
    scantop_kernel<<<1, 32>>>();
    scantile_kernel<<<NTILE, 256>>>();
    fill_kernel<<<(NE + 255) / 256, 256>>>(ei);
    wconv_kernel<<<2 * NL * 32, 256>>>(W1, W2);

    const float* hin = x;
    float* bufs[2] = { h0p, h1p };
    for (int l = 0; l < NL; l++) {
        aggregate_kernel<<<(NN * 32 + 255) / 256, 256>>>(hin);
        float* ho = (l == NL - 1) ? out : bufs[l & 1];
        mlp_mma_kernel<<<NTILES, 512, SMEM_BYTES>>>(
            b1 + (size_t)l * 2 * DD,
            b2 + (size_t)l * DD,
            w1p + (size_t)l * 32768,
            w2p + (size_t)l * 32768,
            ho, (l < NL - 1) ? 1 : 0);
        hin = ho;
    }
}

// round 13
// speedup vs baseline: 1.2811x; 1.0091x over previous
#include <cuda_runtime.h>
#include <cuda_fp16.h>
#include <cstdint>

#define NN 50000
#define NE 600000
#define DD 128
#define NL 5
#define NTILES 391   // ceil(50000/128)

// ---------------- scratch ----------------
__device__ int   g_is64;
__device__ int   g_deg[NN];
__device__ int   g_cursor[NN];
__device__ int   g_rowptr[NN + 1];
__device__ int   g_col[NE];
__device__ float g_h0[NN * DD];
__device__ float g_h1[NN * DD];
__device__ __half g_hh[(size_t)NN * DD];     // packed fp16 copy of h (neighbor gather)
// split z in FRAGMENT-MAJOR tile layout: per 128-row tile, 16384 halves
__device__ __half g_zh[(size_t)NTILES * 16384];
__device__ __half g_zl[(size_t)NTILES * 16384];

// fp16 weights in fragment-major chunk layout:
__device__ __half g_w1[NL * 4 * 8192];
__device__ __half g_w2[NL * 4 * 8192];

#define STILE 1024
#define NTILE ((NN + STILE - 1) / STILE)
__device__ int g_tsum[NTILE];

// ---------------- helpers ----------------
__device__ __forceinline__ float leaky(float v) { return v > 0.f ? v : 0.2f * v; }

__device__ __forceinline__ void split2h(float a, float b, uint32_t& hw, uint32_t& lw) {
    __half ha = __float2half_rn(a);
    __half hb = __float2half_rn(b);
    float ra = a - __half2float(ha);
    float rb = b - __half2float(hb);
    __half la = __float2half_rn(ra);
    __half lb = __float2half_rn(rb);
    hw = (uint32_t)__half_as_ushort(ha) | ((uint32_t)__half_as_ushort(hb) << 16);
    lw = (uint32_t)__half_as_ushort(la) | ((uint32_t)__half_as_ushort(lb) << 16);
}

__device__ __forceinline__ void mma16816h(float* d, const uint32_t* a, const uint32_t* b) {
    asm volatile(
        "mma.sync.aligned.m16n8k16.row.col.f32.f16.f16.f32 "
        "{%0,%1,%2,%3}, {%4,%5,%6,%7}, {%8,%9}, {%0,%1,%2,%3};"
        : "+f"(d[0]), "+f"(d[1]), "+f"(d[2]), "+f"(d[3])
        : "r"(a[0]), "r"(a[1]), "r"(a[2]), "r"(a[3]), "r"(b[0]), "r"(b[1]));
}

__device__ __forceinline__ uint32_t smem_u32(const void* p) {
    uint32_t a;
    asm("{ .reg .u64 t; cvta.to.shared.u64 t, %1; cvt.u32.u64 %0, t; }" : "=r"(a) : "l"(p));
    return a;
}

__device__ __forceinline__ void cpa16(uint32_t dst, const void* src) {
    asm volatile("cp.async.cg.shared.global [%0], [%1], 16;" :: "r"(dst), "l"(src));
}

// ---------------- zero + dtype detect (merged) ----------------
__global__ void zerodetect_kernel(const int* __restrict__ p) {
    int i = blockIdx.x * blockDim.x + threadIdx.x;
    if (i < NN) { g_deg[i] = 0; g_cursor[i] = 0; }
    if (blockIdx.x == 0 && threadIdx.x == 0) {
        int acc = 0;
#pragma unroll
        for (int j = 0; j < 64; j++) acc |= p[2 * j + 1];
        g_is64 = (acc == 0) ? 1 : 0;
    }
}
__device__ __forceinline__ int edge_at(const int* __restrict__ p, int idx) {
    return g_is64 ? p[2 * idx] : p[idx];
}

// ---------------- x -> fp16 copy (layer-0 gather source) ----------------
__global__ void xconv_kernel(const float* __restrict__ x) {
    int i = blockIdx.x * blockDim.x + threadIdx.x;   // i over NN*32 float4s
    if (i < NN * 32) {
        float4 v = __ldg(&((const float4*)x)[i]);
        __half2 p0 = __floats2half2_rn(v.x, v.y);
        __half2 p1 = __floats2half2_rn(v.z, v.w);
        uint2 u;
        u.x = *(uint32_t*)&p0;
        u.y = *(uint32_t*)&p1;
        ((uint2*)g_hh)[i] = u;
    }
}

// ---------------- CSR build ----------------
__global__ void hist_kernel(const int* __restrict__ ei) {
    int e = blockIdx.x * blockDim.x + threadIdx.x;
    if (e < NE) atomicAdd(&g_deg[edge_at(ei, NE + e)], 1);
}
__global__ void reduce_kernel() {
    int b = blockIdx.x, t = threadIdx.x;
    int s = 0;
#pragma unroll
    for (int j = 0; j < 4; j++) {
        int i = b * STILE + t * 4 + j;
        if (i < NN) s += g_deg[i];
    }
#pragma unroll
    for (int o = 16; o; o >>= 1) s += __shfl_down_sync(~0u, s, o);
    __shared__ int ws[8];
    if ((t & 31) == 0) ws[t >> 5] = s;
    __syncthreads();
    if (t == 0) {
        int tot = 0;
#pragma unroll
        for (int w = 0; w < 8; w++) tot += ws[w];
        g_tsum[b] = tot;
    }
}
__global__ void scantop_kernel() {
    if (threadIdx.x == 0) {
        int a = 0;
        for (int i = 0; i < NTILE; i++) { int v = g_tsum[i]; g_tsum[i] = a; a += v; }
    }
}
__global__ void scantile_kernel() {
    int b = blockIdx.x, t = threadIdx.x;
    int v[4], s = 0;
#pragma unroll
    for (int j = 0; j < 4; j++) {
        int i = b * STILE + t * 4 + j;
        int x = (i < NN) ? g_deg[i] : 0;
        s += x; v[j] = s;
    }
    __shared__ int ss[256];
    ss[t] = s;
    __syncthreads();
    for (int o = 1; o < 256; o <<= 1) {
        int x = (t >= o) ? ss[t - o] : 0;
        __syncthreads();
        ss[t] += x;
        __syncthreads();
    }
    int excl = ss[t] - s + g_tsum[b];
#pragma unroll
    for (int j = 0; j < 4; j++) {
        int i = b * STILE + t * 4 + j;
        if (i < NN) g_rowptr[i + 1] = excl + v[j];
    }
    if (b == 0 && t == 0) g_rowptr[0] = 0;
}
__global__ void fill_kernel(const int* __restrict__ ei) {
    int e = blockIdx.x * blockDim.x + threadIdx.x;
    if (e < NE) {
        int src = edge_at(ei, e);
        int dst = edge_at(ei, NE + e);
        int pos = g_rowptr[dst] + atomicAdd(&g_cursor[dst], 1);
        g_col[pos] = src;
    }
}

// ---------------- weight conversion: transpose + fragment-major blocked layout ----------------
__device__ __forceinline__ size_t wfrag_idx(int chunk, int nb, int ksc, int fr, int klocal, int kbit) {
    int word = klocal >> 3;
    int fkk = (klocal & 7) & ~1;
    int ln = fr * 4 + (fkk >> 1);
    return (size_t)chunk * 8192 + (nb * 4 + ksc) * 128 + ln * 4 + word * 2 + kbit;
}

__global__ void wconv_kernel(const float* __restrict__ W1, const float* __restrict__ W2) {
    __shared__ float tile[32][33];
    int b = blockIdx.x;
    int tx = threadIdx.x & 31, ty = threadIdx.x >> 5;   // 32 x 8
    if (b < NL * 32) {
        int l = b >> 5, r = b & 31;
        int kt = r >> 3, nt = r & 7;
        const float* src = W1 + (size_t)l * 32768;
#pragma unroll
        for (int j = 0; j < 4; j++)
            tile[ty * 4 + j][tx] = __ldg(&src[(kt * 32 + ty * 4 + j) * 256 + nt * 32 + tx]);
        __syncthreads();
#pragma unroll
        for (int j = 0; j < 4; j++) {
            float w = tile[tx][ty * 4 + j];
            int n = nt * 32 + ty * 4 + j, k = kt * 32 + tx;
            int chunk = (n >> 7) * 2 + (k >> 6);
            size_t o = (size_t)l * 32768 +
                       wfrag_idx(chunk, (n & 127) >> 3, (k & 63) >> 4, n & 7, k & 15, k & 1);
            g_w1[o] = __float2half_rn(w);
        }
    } else {
        int u = b - NL * 32;
        int l = u >> 5, r = u & 31;
        int kt = r >> 2, nt = r & 3;
        const float* src = W2 + (size_t)l * 32768;
#pragma unroll
        for (int j = 0; j < 4; j++)
            tile[ty * 4 + j][tx] = __ldg(&src[(kt * 32 + ty * 4 + j) * 128 + nt * 32 + tx]);
        __syncthreads();
#pragma unroll
        for (int j = 0; j < 4; j++) {
            float w = tile[tx][ty * 4 + j];
            int n = nt * 32 + ty * 4 + j, k = kt * 32 + tx;
            int chunk = k >> 6;
            size_t o = (size_t)l * 32768 +
                       wfrag_idx(chunk, n >> 3, (k & 63) >> 4, n & 7, k & 15, k & 1);
            g_w2[o] = __float2half_rn(w);
        }
    }
}

// ---------------- aggregation: z = h_self(fp32) + sum(neigh hh fp16), SPLIT fp16, frag-major ----------------
__global__ __launch_bounds__(256) void aggregate_kernel(const float* __restrict__ hin,
                                                        const __half* __restrict__ hh) {
    int node = (blockIdx.x * blockDim.x + threadIdx.x) >> 5;
    int lane = threadIdx.x & 31;
    if (node >= NN) return;
    const float4* hv = (const float4*)hin;
    const uint2* hv2 = (const uint2*)hh;     // row = 32 uint2 (128 halves)
    float4 acc = __ldg(&hv[node * 32 + lane]);   // exact self term
    int beg = g_rowptr[node];
    int end = g_rowptr[node + 1];
    int e = beg;
    for (; e + 4 <= end; e += 4) {
        int s0 = __ldg(&g_col[e]);
        int s1 = __ldg(&g_col[e + 1]);
        int s2 = __ldg(&g_col[e + 2]);
        int s3 = __ldg(&g_col[e + 3]);
        uint2 u0 = __ldg(&hv2[(size_t)s0 * 32 + lane]);
        uint2 u1 = __ldg(&hv2[(size_t)s1 * 32 + lane]);
        uint2 u2 = __ldg(&hv2[(size_t)s2 * 32 + lane]);
        uint2 u3 = __ldg(&hv2[(size_t)s3 * 32 + lane]);
#pragma unroll
        for (int q = 0; q < 4; q++) {
            uint2 u = (q == 0) ? u0 : (q == 1) ? u1 : (q == 2) ? u2 : u3;
            float2 a = __half22float2(*(__half2*)&u.x);
            float2 b = __half22float2(*(__half2*)&u.y);
            acc.x += a.x; acc.y += a.y; acc.z += b.x; acc.w += b.y;
        }
    }
    for (; e < end; e++) {
        int s = __ldg(&g_col[e]);
        uint2 u = __ldg(&hv2[(size_t)s * 32 + lane]);
        float2 a = __half22float2(*(__half2*)&u.x);
        float2 b = __half22float2(*(__half2*)&u.y);
        acc.x += a.x; acc.y += a.y; acc.z += b.x; acc.w += b.y;
    }
    // fragment-major store (128-row tiles): lane owns cols [4*lane, 4*lane+4)
    int tile = node >> 7, rr = node & 127;
    int rb = rr >> 4, fr8 = rr & 15;
    int wrow = fr8 >> 3;
    int fr = fr8 & 7;
    int l3 = lane & 3;
    int klocal = 4 * l3;
    int whigh = (klocal >= 8) ? 2 : 0;
    int lane1 = fr * 4 + ((l3 & 1) ? 2 : 0);
    int w = wrow + whigh;
    size_t base = (size_t)tile * 16384 + (size_t)(rb * 8 + (lane >> 2)) * 256;
    size_t idx1 = base + lane1 * 8 + w * 2;
    size_t idx2 = idx1 + 8;
    uint32_t h0, l0, h1, l1;
    split2h(acc.x, acc.y, h0, l0);
    split2h(acc.z, acc.w, h1, l1);
    *(uint32_t*)(g_zh + idx1) = h0;
    *(uint32_t*)(g_zh + idx2) = h1;
    *(uint32_t*)(g_zl + idx1) = l0;
    *(uint32_t*)(g_zl + idx2) = l1;
}

// ---------------- pipelined HMMA MLP: 128-row tile, 512 threads ----------------
#define SB1_OFF 0
#define SB2_OFF 1024
#define AH_OFF  2048
#define AL_OFF  (AH_OFF + 32768)    // 34816
#define YH_OFF  (AL_OFF + 32768)    // 67584
#define YL_OFF  (YH_OFF + 65536)    // 133120
#define WB_OFF  (YL_OFF + 65536)    // 198656
#define WCH     16384
#define SMEM_BYTES (WB_OFF + 2 * WCH)  // 231424

__device__ __forceinline__ void stage_chunk(uint32_t sb, int i,
    const __half* w1, const __half* w2, int tid)
{
    const __half* src = (i < 4) ? (w1 + (size_t)i * 8192) : (w2 + (size_t)(i - 4) * 8192);
    uint32_t dst = sb + WB_OFF + (uint32_t)(i & 1) * WCH;
#pragma unroll
    for (int j = 0; j < 2; j++) {
        int idx = tid + j * 512;
        cpa16(dst + idx * 16, src + idx * 8);
    }
}

template<int RBS>
__device__ __forceinline__ void gemm4f(const char* smem, int aoh, int aol, int ksbase, int wboff,
                                       int rg, int cg, int lane, float acc[2][4][4])
{
#pragma unroll
    for (int ks = 0; ks < 4; ks++) {
        uint4 ah[2], al[2];
#pragma unroll
        for (int s = 0; s < 2; s++) {
            int off = ((rg * 2 + s) * RBS + ksbase + ks) * 512 + lane * 16;
            ah[s] = *(const uint4*)(smem + aoh + off);
            al[s] = *(const uint4*)(smem + aol + off);
        }
#pragma unroll
        for (int nt = 0; nt < 4; nt++) {
            uint2 b = *(const uint2*)(smem + wboff + ((cg * 4 + nt) * 4 + ks) * 256 + lane * 8);
            uint32_t bh[2] = { b.x, b.y };
#pragma unroll
            for (int s = 0; s < 2; s++) {
                mma16816h(acc[s][nt], (const uint32_t*)&ah[s], bh);
                mma16816h(acc[s][nt], (const uint32_t*)&al[s], bh);
            }
        }
    }
}

__global__ __launch_bounds__(512, 1) void mlp_mma_kernel(
    const float* __restrict__ b1g, const float* __restrict__ b2g,
    const __half* __restrict__ w1, const __half* __restrict__ w2,
    float* __restrict__ out, int do_relu)
{
    extern __shared__ char smem[];
    uint32_t sb = smem_u32(smem);
    int tid = threadIdx.x, lane = tid & 31, wid = tid >> 5;
    int rg = wid & 3, cg = wid >> 2;      // 4 row-groups x 4 col-groups
    int row0 = blockIdx.x * 128;
    float* sb1 = (float*)(smem + SB1_OFF);
    float* sb2 = (float*)(smem + SB2_OFF);

    if (tid < 256) sb1[tid] = __ldg(&b1g[tid]);
    else if (tid < 384) sb2[tid - 256] = __ldg(&b2g[tid - 256]);

    // ---- stage A tile (fragment-major in global): pure linear copy ----
    {
        size_t o = (size_t)blockIdx.x * 16384;
#pragma unroll
        for (int j = 0; j < 4; j++) {
            int idx = tid + j * 512;
            cpa16(sb + AH_OFF + idx * 16, g_zh + o + idx * 8);
            cpa16(sb + AL_OFF + idx * 16, g_zl + o + idx * 8);
        }
    }
    stage_chunk(sb, 0, w1, w2, tid);
    asm volatile("cp.async.commit_group;" ::: "memory");

    int fr = lane >> 2, fk = (lane & 3) * 2;
    float acc[2][4][4];

    for (int c = 0; c < 8; c++) {
        __syncthreads();
        if (c < 7) {
            stage_chunk(sb, c + 1, w1, w2, tid);
            asm volatile("cp.async.commit_group;" ::: "memory");
            asm volatile("cp.async.wait_group 1;" ::: "memory");
        } else {
            asm volatile("cp.async.wait_group 0;" ::: "memory");
        }
        __syncthreads();

        if (c == 0 || c == 2 || c == 4) {
#pragma unroll
            for (int s = 0; s < 2; s++)
#pragma unroll
                for (int nt = 0; nt < 4; nt++)
#pragma unroll
                    for (int q = 0; q < 4; q++) acc[s][nt][q] = 0.f;
        }

        int wboff = WB_OFF + (c & 1) * WCH;
        if (c < 4)
            gemm4f<8>(smem, AH_OFF, AL_OFF, (c & 1) * 4, wboff, rg, cg, lane, acc);
        else
            gemm4f<16>(smem, YH_OFF, YL_OFF, (c - 4) * 4, wboff, rg, cg, lane, acc);

        if (c == 1 || c == 3) {
            // epilogue 1: bias + leaky, split fp16 -> Y (fragment-major, vector STS)
            int nh = c >> 1;
#pragma unroll
            for (int s = 0; s < 2; s++) {
#pragma unroll
                for (int p = 0; p < 2; p++) {
                    float* aE = acc[s][2 * p];
                    float* aO = acc[s][2 * p + 1];
                    int cglE = nh * 128 + cg * 32 + (2 * p) * 8 + fk;
                    float bE0 = sb1[cglE], bE1 = sb1[cglE + 1];
                    float bO0 = sb1[cglE + 8], bO1 = sb1[cglE + 9];
                    uint4 hv, lv;
                    split2h(leaky(aE[0] + bE0), leaky(aE[1] + bE1), hv.x, lv.x);
                    split2h(leaky(aE[2] + bE0), leaky(aE[3] + bE1), hv.y, lv.y);
                    split2h(leaky(aO[0] + bO0), leaky(aO[1] + bO1), hv.z, lv.z);
                    split2h(leaky(aO[2] + bO0), leaky(aO[3] + bO1), hv.w, lv.w);
                    int off = ((rg * 2 + s) * 16 + nh * 8 + cg * 2 + p) * 512 + lane * 16;
                    *(uint4*)(smem + YH_OFF + off) = hv;
                    *(uint4*)(smem + YL_OFF + off) = lv;
                }
            }
        }
    }

    // ---- epilogue 2: bias [+ leaky] -> global fp32 (+ fp16 hh copy for next gather) ----
#pragma unroll
    for (int s = 0; s < 2; s++) {
        int r = rg * 32 + s * 16 + fr;
#pragma unroll
        for (int nt = 0; nt < 4; nt++) {
            int c = cg * 32 + nt * 8 + fk;
            float bA = sb2[c], bB = sb2[c + 1];
            int node = row0 + r;
            if (node < NN) {
                float v0 = acc[s][nt][0] + bA;
                float v1 = acc[s][nt][1] + bB;
                if (do_relu) { v0 = leaky(v0); v1 = leaky(v1); }
                *(float2*)(out + (size_t)node * DD + c) = make_float2(v0, v1);
                if (do_relu) {
                    __half2 hp = __floats2half2_rn(v0, v1);
                    *(uint32_t*)(g_hh + (size_t)node * DD + c) = *(uint32_t*)&hp;
                }
            }
            if (node + 8 < NN) {
                float v0 = acc[s][nt][2] + bA;
                float v1 = acc[s][nt][3] + bB;
                if (do_relu) { v0 = leaky(v0); v1 = leaky(v1); }
                *(float2*)(out + (size_t)(node + 8) * DD + c) = make_float2(v0, v1);
                if (do_relu) {
                    __half2 hp = __floats2half2_rn(v0, v1);
                    *(uint32_t*)(g_hh + (size_t)(node + 8) * DD + c) = *(uint32_t*)&hp;
                }
            }
        }
    }
}

// ---------------- launch ----------------
extern "C" void kernel_launch(void* const* d_in, const int* in_sizes, int n_in,
                              void* d_out, int out_size) {
    const float* x  = (const float*)d_in[0];
    const int*   ei = (const int*)d_in[1];
    const float* W1 = (const float*)d_in[2];
    const float* b1 = (const float*)d_in[3];
    const float* W2 = (const float*)d_in[4];
    const float* b2 = (const float*)d_in[5];
    float* out = (float*)d_out;

    float *h0p, *h1p;
    cudaGetSymbolAddress((void**)&h0p, g_h0);
    cudaGetSymbolAddress((void**)&h1p, g_h1);
    __half *w1p, *w2p, *hhp;
    cudaGetSymbolAddress((void**)&w1p, g_w1);
    cudaGetSymbolAddress((void**)&w2p, g_w2);
    cudaGetSymbolAddress((void**)&hhp, g_hh);

    cudaFuncSetAttribute(mlp_mma_kernel, cudaFuncAttributeMaxDynamicSharedMemorySize, SMEM_BYTES);

    zerodetect_kernel<<<(NN + 1023) / 1024, 1024>>>(ei);
    xconv_kernel<<<(NN * 32 + 255) / 256, 256>>>(x);
    hist_kernel<<<(NE + 255) / 256, 256>>>(ei);
    reduce_kernel<<<NTILE, 256>>>();
    scantop_kernel<<<1, 32>>>();
    scantile_kernel<<<NTILE, 256>>>();
    fill_kernel<<<(NE + 255) / 256, 256>>>(ei);
    wconv_kernel<<<2 * NL * 32, 256>>>(W1, W2);

    const float* hin = x;
    float* bufs[2] = { h0p, h1p };
    for (int l = 0; l < NL; l++) {
        aggregate_kernel<<<(NN * 32 + 255) / 256, 256>>>(hin, hhp);
        float* ho = (l == NL - 1) ? out : bufs[l & 1];
        mlp_mma_kernel<<<NTILES, 512, SMEM_BYTES>>>(
            b1 + (size_t)l * 2 * DD,
            b2 + (size_t)l * DD,
            w1p + (size_t)l * 32768,
            w2p + (size_t)l * 32768,
            ho, (l < NL - 1) ? 1 : 0);
        hin = ho;
    }
}